// round 1
// baseline (speedup 1.0000x reference)
#include <cuda_runtime.h>

// Decoder_21225728377092 — fully fused single-kernel implementation.
//
// Key simplification: softmax over the seq axis of a seq-constant input is
// uniform 1/S, so "attention" output = teo / 4096 (teo = q^2 - k*v with
// k from s-1 (clamp at 0) and v from s+1 (clamp at S-1)).
// Total seq dependency radius across 8 mha stages = 8 -> tile + 8 halo.

#define L    4
#define D    6
#define DFF  64
#define SEQ  4096
#define NB   128
#define TILE 512
#define HALO 8
#define EXT  (TILE + 2 * HALO)   // 528 threads per block
#define EPSF 1e-6f
#define INV_S (1.0f / 4096.0f)

__device__ __forceinline__ void ln6(float* v, const float* w, const float* b) {
    float mu = (v[0] + v[1] + v[2] + v[3] + v[4] + v[5]) * (1.0f / 6.0f);
    float var = 0.0f;
#pragma unroll
    for (int d = 0; d < D; d++) {
        float t = v[d] - mu;
        var = fmaf(t, t, var);
    }
    var *= (1.0f / 6.0f);
    float r = rsqrtf(var + EPSF);
#pragma unroll
    for (int d = 0; d < D; d++) {
        v[d] = (v[d] - mu) * r * w[d] + b[d];
    }
}

__global__ __launch_bounds__(EXT) void decoder_fused_kernel(
    const float* __restrict__ g_x,
    const float* __restrict__ g_dec_w, const float* __restrict__ g_dec_b,
    const float* __restrict__ g_qw, const float* __restrict__ g_qb,
    const float* __restrict__ g_kw, const float* __restrict__ g_kb,
    const float* __restrict__ g_vw, const float* __restrict__ g_vb,
    const float* __restrict__ g_mlw, const float* __restrict__ g_mlb,
    const float* __restrict__ g_w1, const float* __restrict__ g_b1,
    const float* __restrict__ g_w2, const float* __restrict__ g_b2,
    const float* __restrict__ g_flw, const float* __restrict__ g_flb,
    float* __restrict__ g_out)
{
    // Shared: seq-exchange buffer (SoA, conflict-free) + all weights.
    __shared__ __align__(16) float xs[D][EXT + 2];       // slot i -> local pos i-1
    __shared__ __align__(16) float w1s[L][DFF][8];       // [l][f][d], rows padded to 8
    __shared__ __align__(16) float w2ts[L][DFF][8];      // transposed: [l][f][d] = w2[l][d][f]
    __shared__ float b1s[L][DFF];
    __shared__ float s_dec[2][D];                        // dec_ln w, b
    __shared__ float s_att[L * 2][8][D];                 // [la][qw qb kw kb vw vb mlw mlb][d]
    __shared__ float s_ffn[3][L][D];                     // [b2 | ffn_ln_w | ffn_ln_b][l][d]

    const int tid = threadIdx.x;

    // ---- cooperative weight staging ----
    for (int i = tid; i < L * DFF * D; i += EXT) {
        int l = i / (DFF * D);
        int f = (i / D) % DFF;
        int d = i % D;
        w1s[l][f][d] = g_w1[i];                 // g_w1: [L][DFF][D]
    }
    for (int i = tid; i < L * D * DFF; i += EXT) {
        int l = i / (D * DFF);
        int r = i % (D * DFF);
        int d = r / DFF;
        int f = r % DFF;
        w2ts[l][f][d] = g_w2[i];                // g_w2: [L][D][DFF]
    }
    for (int i = tid; i < L * DFF; i += EXT) b1s[i / DFF][i % DFF] = g_b1[i];
    if (tid < D) { s_dec[0][tid] = g_dec_w[tid]; s_dec[1][tid] = g_dec_b[tid]; }
    for (int i = tid; i < L * 2 * D; i += EXT) {
        int la = i / D, d = i % D;
        s_att[la][0][d] = g_qw[i];  s_att[la][1][d] = g_qb[i];
        s_att[la][2][d] = g_kw[i];  s_att[la][3][d] = g_kb[i];
        s_att[la][4][d] = g_vw[i];  s_att[la][5][d] = g_vb[i];
        s_att[la][6][d] = g_mlw[i]; s_att[la][7][d] = g_mlb[i];
    }
    for (int i = tid; i < L * D; i += EXT) {
        int l = i / D, d = i % D;
        s_ffn[0][l][d] = g_b2[i];
        s_ffn[1][l][d] = g_flw[i];
        s_ffn[2][l][d] = g_flb[i];
    }
    if (tid < D) { xs[tid][0] = 0.0f; xs[tid][EXT + 1] = 0.0f; }  // pads

    // ---- load my position ----
    const int b = blockIdx.y;
    const int s = blockIdx.x * TILE - HALO + tid;        // may be out of [0,SEQ)
    const int sc = min(max(s, 0), SEQ - 1);
    const float* xin = g_x + ((size_t)b * SEQ + sc) * D;

    float x[D];
    {
        // 24B per position, 8B-aligned -> 3x float2
        const float2* p = reinterpret_cast<const float2*>(xin);
        float2 a0 = p[0], a1 = p[1], a2 = p[2];
        x[0] = a0.x; x[1] = a0.y; x[2] = a1.x; x[3] = a1.y; x[4] = a2.x; x[5] = a2.y;
    }

    __syncthreads();                                     // weights ready

    ln6(x, s_dec[0], s_dec[1]);

    const bool left_edge  = (s <= 0);
    const bool right_edge = (s >= SEQ - 1);

#pragma unroll 1
    for (int l = 0; l < L; l++) {
        // ---- two attention blocks ----
#pragma unroll
        for (int a = 0; a < 2; a++) {
            const int la = l * 2 + a;
            __syncthreads();                             // prior reads done
#pragma unroll
            for (int d = 0; d < D; d++) xs[d][tid + 1] = x[d];
            __syncthreads();

            float nx[D];
#pragma unroll
            for (int d = 0; d < D; d++) {
                float xl = left_edge  ? x[d] : xs[d][tid];
                float xr = right_edge ? x[d] : xs[d][tid + 2];
                float q  = fmaf(x[d], s_att[la][0][d], s_att[la][1][d]);
                float kk = fmaf(xl,   s_att[la][2][d], s_att[la][3][d]);
                float vv = fmaf(xr,   s_att[la][4][d], s_att[la][5][d]);
                float teo = fmaf(q, q, -(kk * vv));
                nx[d] = fmaf(teo, INV_S, x[d]);          // scores*teo + residual
            }
            ln6(nx, s_att[la][6], s_att[la][7]);
#pragma unroll
            for (int d = 0; d < D; d++) x[d] = nx[d];
        }

        // ---- FFN: y = W2 relu(W1 x + b1) + b2 + x ----
        float y[D];
#pragma unroll
        for (int d = 0; d < D; d++) y[d] = x[d] + s_ffn[0][l][d];

#pragma unroll 8
        for (int f = 0; f < DFF; f++) {
            const float4 wa = *reinterpret_cast<const float4*>(&w1s[l][f][0]);
            const float2 wb = *reinterpret_cast<const float2*>(&w1s[l][f][4]);
            float hf = b1s[l][f];
            hf = fmaf(wa.x, x[0], hf);
            hf = fmaf(wa.y, x[1], hf);
            hf = fmaf(wa.z, x[2], hf);
            hf = fmaf(wa.w, x[3], hf);
            hf = fmaf(wb.x, x[4], hf);
            hf = fmaf(wb.y, x[5], hf);
            hf = fmaxf(hf, 0.0f);
            const float4 va = *reinterpret_cast<const float4*>(&w2ts[l][f][0]);
            const float2 vb = *reinterpret_cast<const float2*>(&w2ts[l][f][4]);
            y[0] = fmaf(hf, va.x, y[0]);
            y[1] = fmaf(hf, va.y, y[1]);
            y[2] = fmaf(hf, va.z, y[2]);
            y[3] = fmaf(hf, va.w, y[3]);
            y[4] = fmaf(hf, vb.x, y[4]);
            y[5] = fmaf(hf, vb.y, y[5]);
        }
        ln6(y, s_ffn[1][l], s_ffn[2][l]);
#pragma unroll
        for (int d = 0; d < D; d++) x[d] = y[d];
    }

    // ---- write interior tile ----
    if (tid >= HALO && tid < HALO + TILE) {
        float* o = g_out + ((size_t)b * SEQ + s) * D;
        float2* p = reinterpret_cast<float2*>(o);
        p[0] = make_float2(x[0], x[1]);
        p[1] = make_float2(x[2], x[3]);
        p[2] = make_float2(x[4], x[5]);
    }
}

extern "C" void kernel_launch(void* const* d_in, const int* in_sizes, int n_in,
                              void* d_out, int out_size) {
    // metadata order:
    // 0 x_batch, 1 enc_output(unused), 2 dec_ln_w, 3 dec_ln_b,
    // 4 qw, 5 qb, 6 kw, 7 kb, 8 vw, 9 vb, 10 ln1_w(unused), 11 ln1_b(unused),
    // 12 mha_ln_w, 13 mha_ln_b, 14 ffn_w1, 15 ffn_b1, 16 ffn_w2, 17 ffn_b2,
    // 18 ffn_ln_w, 19 ffn_ln_b
    dim3 grid(SEQ / TILE, NB);
    decoder_fused_kernel<<<grid, EXT>>>(
        (const float*)d_in[0],
        (const float*)d_in[2],  (const float*)d_in[3],
        (const float*)d_in[4],  (const float*)d_in[5],
        (const float*)d_in[6],  (const float*)d_in[7],
        (const float*)d_in[8],  (const float*)d_in[9],
        (const float*)d_in[12], (const float*)d_in[13],
        (const float*)d_in[14], (const float*)d_in[15],
        (const float*)d_in[16], (const float*)d_in[17],
        (const float*)d_in[18], (const float*)d_in[19],
        (float*)d_out);
}

// round 2
// speedup vs baseline: 1.0785x; 1.0785x over previous
#include <cuda_runtime.h>

// Decoder_21225728377092 — fused, 4 positions/thread, packed f32x2 math.
//
// Math identity: softmax over seq of a seq-constant tensor is uniform 1/4096,
// so attention out = teo/4096, teo = q^2 - k*v, k from s-1 (clamp 0),
// v from s+1 (clamp SEQ-1). 8 mha stages -> total seq radius 8 -> halo 8.

#define L    4
#define D    6
#define DFF  64
#define SEQ  4096
#define NB   128
#define TILE 1024
#define HALO 8
#define P    4
#define TPB  ((TILE + 2 * HALO) / P)   // 260 threads
#define EPSF 1e-6f
#define INV_S (1.0f / 4096.0f)

typedef unsigned long long u64;

__device__ __forceinline__ u64 pk(float a, float b) {
    u64 r; asm("mov.b64 %0, {%1,%2};" : "=l"(r) : "f"(a), "f"(b)); return r;
}
__device__ __forceinline__ float2 up(u64 v) {
    float2 r; asm("mov.b64 {%0,%1}, %2;" : "=f"(r.x), "=f"(r.y) : "l"(v)); return r;
}
__device__ __forceinline__ u64 f2fma(u64 a, u64 b, u64 c) {
    u64 d; asm("fma.rn.f32x2 %0,%1,%2,%3;" : "=l"(d) : "l"(a), "l"(b), "l"(c)); return d;
}
__device__ __forceinline__ u64 f2mul(u64 a, u64 b) {
    u64 d; asm("mul.rn.f32x2 %0,%1,%2;" : "=l"(d) : "l"(a), "l"(b)); return d;
}
__device__ __forceinline__ u64 f2add(u64 a, u64 b) {
    u64 d; asm("add.rn.f32x2 %0,%1,%2;" : "=l"(d) : "l"(a), "l"(b)); return d;
}
__device__ __forceinline__ u64 relu2(u64 v) {
    float2 t = up(v);
    return pk(fmaxf(t.x, 0.0f), fmaxf(t.y, 0.0f));
}

struct Smem {
    u64 w1p[L][DFF][8];     // [l][f][0..5]=w1 pairs, [6]=b1 pair, [7] pad
    u64 w2p[L][DFF][8];     // [l][f][0..5]=w2[l][d][f] pairs
    u64 attp[2 * L][8][8];  // [stage][qw qb kw kb vw vb lnw lnb][d]
    u64 ffnlnp[L][2][8];    // [l][w|b][d]
    u64 b2p[L][8];          // [l][d]
    u64 decp[2][8];         // [w|b][d]
    float xfirst[D][TPB + 2];
    float xlast[D][TPB + 2];
};

// packed layernorm over D=6 for one position-pair
__device__ __forceinline__ void ln6p(u64* v, const u64* w, const u64* b) {
    u64 s = f2add(f2add(f2add(v[0], v[1]), f2add(v[2], v[3])), f2add(v[4], v[5]));
    u64 nmu = f2mul(s, pk(-1.0f / 6.0f, -1.0f / 6.0f));
    u64 t[D];
    u64 var;
#pragma unroll
    for (int d = 0; d < D; d++) {
        t[d] = f2add(v[d], nmu);
        var = (d == 0) ? f2mul(t[0], t[0]) : f2fma(t[d], t[d], var);
    }
    float2 vv = up(var);
    float rx = rsqrtf(fmaf(vv.x, 1.0f / 6.0f, EPSF));
    float ry = rsqrtf(fmaf(vv.y, 1.0f / 6.0f, EPSF));
    u64 rp = pk(rx, ry);
#pragma unroll
    for (int d = 0; d < D; d++) {
        v[d] = f2fma(f2mul(t[d], rp), w[d], b[d]);
    }
}

__global__ __launch_bounds__(TPB, 2) void decoder_fused_kernel(
    const float* __restrict__ g_x,
    const float* __restrict__ g_dec_w, const float* __restrict__ g_dec_b,
    const float* __restrict__ g_qw, const float* __restrict__ g_qb,
    const float* __restrict__ g_kw, const float* __restrict__ g_kb,
    const float* __restrict__ g_vw, const float* __restrict__ g_vb,
    const float* __restrict__ g_mlw, const float* __restrict__ g_mlb,
    const float* __restrict__ g_w1, const float* __restrict__ g_b1,
    const float* __restrict__ g_w2, const float* __restrict__ g_b2,
    const float* __restrict__ g_flw, const float* __restrict__ g_flb,
    float* __restrict__ g_out)
{
    extern __shared__ __align__(16) unsigned char smem_raw[];
    Smem* sm = reinterpret_cast<Smem*>(smem_raw);

    const int tid = threadIdx.x;

    // ---------------- weight staging (packed broadcast pairs) ----------------
    for (int i = tid; i < L * DFF * D; i += TPB) {
        int l = i / (DFF * D), f = (i / D) % DFF, d = i % D;
        float w = g_w1[i];
        sm->w1p[l][f][d] = pk(w, w);
    }
    for (int i = tid; i < L * DFF; i += TPB) {
        float w = g_b1[i];
        sm->w1p[i / DFF][i % DFF][6] = pk(w, w);
    }
    for (int i = tid; i < L * D * DFF; i += TPB) {
        int l = i / (D * DFF), d = (i / DFF) % D, f = i % DFF;
        float w = g_w2[i];
        sm->w2p[l][f][d] = pk(w, w);
    }
    for (int i = tid; i < 2 * L * D; i += TPB) {
        int la = i / D, d = i % D;
        sm->attp[la][0][d] = pk(g_qw[i], g_qw[i]);
        sm->attp[la][1][d] = pk(g_qb[i], g_qb[i]);
        sm->attp[la][2][d] = pk(g_kw[i], g_kw[i]);
        sm->attp[la][3][d] = pk(g_kb[i], g_kb[i]);
        sm->attp[la][4][d] = pk(g_vw[i], g_vw[i]);
        sm->attp[la][5][d] = pk(g_vb[i], g_vb[i]);
        sm->attp[la][6][d] = pk(g_mlw[i], g_mlw[i]);
        sm->attp[la][7][d] = pk(g_mlb[i], g_mlb[i]);
    }
    for (int i = tid; i < L * D; i += TPB) {
        int l = i / D, d = i % D;
        sm->ffnlnp[l][0][d] = pk(g_flw[i], g_flw[i]);
        sm->ffnlnp[l][1][d] = pk(g_flb[i], g_flb[i]);
        sm->b2p[l][d] = pk(g_b2[i], g_b2[i]);
    }
    if (tid < D) {
        sm->decp[0][tid] = pk(g_dec_w[tid], g_dec_w[tid]);
        sm->decp[1][tid] = pk(g_dec_b[tid], g_dec_b[tid]);
        sm->xfirst[tid][0] = 0.0f;         sm->xlast[tid][0] = 0.0f;
        sm->xfirst[tid][TPB + 1] = 0.0f;   sm->xlast[tid][TPB + 1] = 0.0f;
    }

    // ---------------- load 4 positions ----------------
    const int bb = blockIdx.y;
    const int s0 = blockIdx.x * TILE - HALO + P * tid;
    const float* xbase = g_x + (size_t)bb * SEQ * D;

    float x[P][D];
    if (s0 >= 0 && s0 <= SEQ - P) {
        float tmp[P * D];
        const float4* p = reinterpret_cast<const float4*>(xbase + (size_t)s0 * D);
#pragma unroll
        for (int k = 0; k < P * D / 4; k++) reinterpret_cast<float4*>(tmp)[k] = p[k];
#pragma unroll
        for (int i = 0; i < P; i++)
#pragma unroll
            for (int d = 0; d < D; d++) x[i][d] = tmp[i * D + d];
    } else {
#pragma unroll
        for (int i = 0; i < P; i++) {
            int sc = min(max(s0 + i, 0), SEQ - 1);
            const float2* p = reinterpret_cast<const float2*>(xbase + (size_t)sc * D);
            float2 a0 = p[0], a1 = p[1], a2 = p[2];
            x[i][0] = a0.x; x[i][1] = a0.y; x[i][2] = a1.x;
            x[i][3] = a1.y; x[i][4] = a2.x; x[i][5] = a2.y;
        }
    }

    __syncthreads();   // weights visible

    // ---------------- dec layernorm (packed) ----------------
    {
        u64 v01[D], v23[D];
#pragma unroll
        for (int d = 0; d < D; d++) { v01[d] = pk(x[0][d], x[1][d]); v23[d] = pk(x[2][d], x[3][d]); }
        ln6p(v01, &sm->decp[0][0], &sm->decp[1][0]);
        ln6p(v23, &sm->decp[0][0], &sm->decp[1][0]);
#pragma unroll
        for (int d = 0; d < D; d++) {
            float2 a = up(v01[d]), b = up(v23[d]);
            x[0][d] = a.x; x[1][d] = a.y; x[2][d] = b.x; x[3][d] = b.y;
        }
    }

    const bool edgeL = (s0 == 0);
    const bool edgeR = (s0 == SEQ - P);
    const u64 INV2   = pk(INV_S, INV_S);
    const u64 NINV2  = pk(-INV_S, -INV_S);

#pragma unroll 1
    for (int l = 0; l < L; l++) {
        // ---------------- two attention+LN stages ----------------
#pragma unroll
        for (int a = 0; a < 2; a++) {
            const int la = l * 2 + a;
            __syncthreads();
#pragma unroll
            for (int d = 0; d < D; d++) {
                sm->xfirst[d][tid + 1] = x[0][d];
                sm->xlast[d][tid + 1]  = x[3][d];
            }
            __syncthreads();

            u64 nx01[D], nx23[D];
            const u64* ap = &sm->attp[la][0][0];
#pragma unroll
            for (int d = 0; d < D; d++) {
                float lin = sm->xlast[d][tid];
                float rin = sm->xfirst[d][tid + 2];
                if (edgeL) lin = x[0][d];
                if (edgeR) rin = x[3][d];
                u64 a01 = pk(x[0][d], x[1][d]);
                u64 a23 = pk(x[2][d], x[3][d]);
                u64 l01 = pk(lin, x[0][d]);
                u64 m12 = pk(x[1][d], x[2][d]);   // serves as l23 and r01
                u64 r23 = pk(x[3][d], rin);
                u64 qwp = ap[0 * 8 + d], qbp = ap[1 * 8 + d];
                u64 kwp = ap[2 * 8 + d], kbp = ap[3 * 8 + d];
                u64 vwp = ap[4 * 8 + d], vbp = ap[5 * 8 + d];
                u64 q01 = f2fma(a01, qwp, qbp);
                u64 q23 = f2fma(a23, qwp, qbp);
                u64 k01 = f2fma(l01, kwp, kbp);
                u64 k23 = f2fma(m12, kwp, kbp);
                u64 v01 = f2fma(m12, vwp, vbp);
                u64 v23 = f2fma(r23, vwp, vbp);
                u64 kv01 = f2mul(k01, v01), kv23 = f2mul(k23, v23);
                u64 qq01 = f2mul(q01, q01), qq23 = f2mul(q23, q23);
                nx01[d] = f2fma(qq01, INV2, f2fma(kv01, NINV2, a01));
                nx23[d] = f2fma(qq23, INV2, f2fma(kv23, NINV2, a23));
            }
            ln6p(nx01, ap + 6 * 8, ap + 7 * 8);
            ln6p(nx23, ap + 6 * 8, ap + 7 * 8);
#pragma unroll
            for (int d = 0; d < D; d++) {
                float2 p0 = up(nx01[d]), p1 = up(nx23[d]);
                x[0][d] = p0.x; x[1][d] = p0.y; x[2][d] = p1.x; x[3][d] = p1.y;
            }
        }

        // ---------------- FFN (packed, weights pre-paired in shared) ----------------
        u64 xp01[D], xp23[D], y01[D], y23[D];
#pragma unroll
        for (int d = 0; d < D; d++) {
            xp01[d] = pk(x[0][d], x[1][d]);
            xp23[d] = pk(x[2][d], x[3][d]);
            u64 b2 = sm->b2p[l][d];
            y01[d] = f2add(xp01[d], b2);
            y23[d] = f2add(xp23[d], b2);
        }
        const u64* w1r = &sm->w1p[l][0][0];
        const u64* w2r = &sm->w2p[l][0][0];
#pragma unroll 8
        for (int f = 0; f < DFF; f++) {
            ulonglong2 wa = *reinterpret_cast<const ulonglong2*>(w1r + f * 8 + 0);
            ulonglong2 wb = *reinterpret_cast<const ulonglong2*>(w1r + f * 8 + 2);
            ulonglong2 wc = *reinterpret_cast<const ulonglong2*>(w1r + f * 8 + 4);
            u64 b1 = w1r[f * 8 + 6];
            u64 h01 = f2fma(xp01[0], wa.x, b1);
            u64 h23 = f2fma(xp23[0], wa.x, b1);
            h01 = f2fma(xp01[1], wa.y, h01);  h23 = f2fma(xp23[1], wa.y, h23);
            h01 = f2fma(xp01[2], wb.x, h01);  h23 = f2fma(xp23[2], wb.x, h23);
            h01 = f2fma(xp01[3], wb.y, h01);  h23 = f2fma(xp23[3], wb.y, h23);
            h01 = f2fma(xp01[4], wc.x, h01);  h23 = f2fma(xp23[4], wc.x, h23);
            h01 = f2fma(xp01[5], wc.y, h01);  h23 = f2fma(xp23[5], wc.y, h23);
            h01 = relu2(h01);
            h23 = relu2(h23);
            ulonglong2 va = *reinterpret_cast<const ulonglong2*>(w2r + f * 8 + 0);
            ulonglong2 vb = *reinterpret_cast<const ulonglong2*>(w2r + f * 8 + 2);
            ulonglong2 vc = *reinterpret_cast<const ulonglong2*>(w2r + f * 8 + 4);
            y01[0] = f2fma(h01, va.x, y01[0]);  y23[0] = f2fma(h23, va.x, y23[0]);
            y01[1] = f2fma(h01, va.y, y01[1]);  y23[1] = f2fma(h23, va.y, y23[1]);
            y01[2] = f2fma(h01, vb.x, y01[2]);  y23[2] = f2fma(h23, vb.x, y23[2]);
            y01[3] = f2fma(h01, vb.y, y01[3]);  y23[3] = f2fma(h23, vb.y, y23[3]);
            y01[4] = f2fma(h01, vc.x, y01[4]);  y23[4] = f2fma(h23, vc.x, y23[4]);
            y01[5] = f2fma(h01, vc.y, y01[5]);  y23[5] = f2fma(h23, vc.y, y23[5]);
        }
        ln6p(y01, &sm->ffnlnp[l][0][0], &sm->ffnlnp[l][1][0]);
        ln6p(y23, &sm->ffnlnp[l][0][0], &sm->ffnlnp[l][1][0]);
#pragma unroll
        for (int d = 0; d < D; d++) {
            float2 p0 = up(y01[d]), p1 = up(y23[d]);
            x[0][d] = p0.x; x[1][d] = p0.y; x[2][d] = p1.x; x[3][d] = p1.y;
        }
    }

    // ---------------- write interior ----------------
    if (tid >= HALO / P && tid < TPB - HALO / P) {
        float tmp[P * D];
#pragma unroll
        for (int i = 0; i < P; i++)
#pragma unroll
            for (int d = 0; d < D; d++) tmp[i * D + d] = x[i][d];
        float4* o = reinterpret_cast<float4*>(g_out + ((size_t)bb * SEQ + s0) * D);
#pragma unroll
        for (int k = 0; k < P * D / 4; k++) o[k] = reinterpret_cast<float4*>(tmp)[k];
    }
}

extern "C" void kernel_launch(void* const* d_in, const int* in_sizes, int n_in,
                              void* d_out, int out_size) {
    cudaFuncSetAttribute(decoder_fused_kernel,
                         cudaFuncAttributeMaxDynamicSharedMemorySize,
                         (int)sizeof(Smem));
    dim3 grid(SEQ / TILE, NB);
    decoder_fused_kernel<<<grid, TPB, sizeof(Smem)>>>(
        (const float*)d_in[0],
        (const float*)d_in[2],  (const float*)d_in[3],
        (const float*)d_in[4],  (const float*)d_in[5],
        (const float*)d_in[6],  (const float*)d_in[7],
        (const float*)d_in[8],  (const float*)d_in[9],
        (const float*)d_in[12], (const float*)d_in[13],
        (const float*)d_in[14], (const float*)d_in[15],
        (const float*)d_in[16], (const float*)d_in[17],
        (const float*)d_in[18], (const float*)d_in[19],
        (float*)d_out);
}

// round 3
// speedup vs baseline: 1.4043x; 1.3020x over previous
#include <cuda_runtime.h>

// Decoder_21225728377092 — fused, warp-self-contained tiles, shfl exchange,
// packed f32x2 math, exact single-wave launch (4736 warps = 148 SM x 32).
//
// Math identity: softmax over seq of a seq-constant tensor is uniform 1/4096,
// so attention out = teo/4096, teo = q^2 - k*v, k from s-1 (clamp 0),
// v from s+1 (clamp SEQ-1). 8 mha stages -> seq radius 8 -> per-warp halo 8.

#define L    4
#define D    6
#define DFF  64
#define SEQ  4096
#define NB   128
#define P    4
#define INT_W 112                 // interior positions per warp (128 slots - 16 halo)
#define WPR  37                   // warps per row: 37*112 >= 4096 (last overlaps)
#define WPB  8                    // warps per block
#define TPB  (WPB * 32)           // 256
#define NBLK ((NB * WPR + WPB - 1) / WPB)   // 592 = 148*4
#define EPSF 1e-6f
#define INV_S (1.0f / 4096.0f)
#define FULL 0xffffffffu

typedef unsigned long long u64;

__device__ __forceinline__ u64 pk(float a, float b) {
    u64 r; asm("mov.b64 %0, {%1,%2};" : "=l"(r) : "f"(a), "f"(b)); return r;
}
__device__ __forceinline__ float2 up(u64 v) {
    float2 r; asm("mov.b64 {%0,%1}, %2;" : "=f"(r.x), "=f"(r.y) : "l"(v)); return r;
}
__device__ __forceinline__ u64 f2fma(u64 a, u64 b, u64 c) {
    u64 d; asm("fma.rn.f32x2 %0,%1,%2,%3;" : "=l"(d) : "l"(a), "l"(b), "l"(c)); return d;
}
__device__ __forceinline__ u64 f2mul(u64 a, u64 b) {
    u64 d; asm("mul.rn.f32x2 %0,%1,%2;" : "=l"(d) : "l"(a), "l"(b)); return d;
}
__device__ __forceinline__ u64 f2add(u64 a, u64 b) {
    u64 d; asm("add.rn.f32x2 %0,%1,%2;" : "=l"(d) : "l"(a), "l"(b)); return d;
}
__device__ __forceinline__ u64 relu2(u64 v) {
    float2 t = up(v);
    return pk(fmaxf(t.x, 0.0f), fmaxf(t.y, 0.0f));
}

struct Smem {
    u64 w1p[L][DFF][8];     // [l][f][0..5]=w1 pairs, [6]=b1 pair, [7] pad
    u64 w2p[L][DFF][8];     // [l][f][0..5]=w2[l][d][f] pairs
    u64 attp[2 * L][8][8];  // [stage][qw qb kw kb vw vb lnw lnb][d]
    u64 ffnlnp[L][2][8];    // [l][w|b][d]
    u64 b2p[L][8];          // [l][d]
    u64 decp[2][8];         // [w|b][d]
};

// packed layernorm over D=6 on v01/v23 in place (two position-pairs)
__device__ __forceinline__ void ln6p(u64* v, const u64* w, const u64* b) {
    u64 s  = f2add(f2add(f2add(v[0], v[1]), f2add(v[2], v[3])), f2add(v[4], v[5]));
    u64 ss = f2mul(v[0], v[0]);
#pragma unroll
    for (int d = 1; d < D; d++) ss = f2fma(v[d], v[d], ss);
    float2 sf = up(s), ssf = up(ss);
    float mux = sf.x * (1.0f / 6.0f), muy = sf.y * (1.0f / 6.0f);
    float varx = fmaf(ssf.x, 1.0f / 6.0f, -mux * mux);
    float vary = fmaf(ssf.y, 1.0f / 6.0f, -muy * muy);
    float rx = rsqrtf(varx + EPSF);
    float ry = rsqrtf(vary + EPSF);
    u64 rp  = pk(rx, ry);
    u64 nmu = pk(-mux, -muy);
#pragma unroll
    for (int d = 0; d < D; d++) {
        u64 rw = f2mul(rp, w[d]);
        v[d] = f2fma(v[d], rw, f2fma(nmu, rw, b[d]));
    }
}

__global__ __launch_bounds__(TPB, 4) void decoder_fused_kernel(
    const float* __restrict__ g_x,
    const float* __restrict__ g_dec_w, const float* __restrict__ g_dec_b,
    const float* __restrict__ g_qw, const float* __restrict__ g_qb,
    const float* __restrict__ g_kw, const float* __restrict__ g_kb,
    const float* __restrict__ g_vw, const float* __restrict__ g_vb,
    const float* __restrict__ g_mlw, const float* __restrict__ g_mlb,
    const float* __restrict__ g_w1, const float* __restrict__ g_b1,
    const float* __restrict__ g_w2, const float* __restrict__ g_b2,
    const float* __restrict__ g_flw, const float* __restrict__ g_flb,
    float* __restrict__ g_out)
{
    __shared__ Smem sm;
    const int tid  = threadIdx.x;
    const int lane = tid & 31;
    const int warp = tid >> 5;

    // ---------------- global warp -> (row, tile) ----------------
    const unsigned g = (unsigned)blockIdx.x * WPB + warp;   // < 4736
    const unsigned row = g / WPR;
    const unsigned w   = g - row * WPR;
    const int istart = min((int)w * INT_W, SEQ - INT_W);
    const int s0 = istart - 8 + P * lane;

    // ---------------- load my 4 positions (overlap with staging) ----------------
    const float* xbase = g_x + (size_t)row * SEQ * D;
    float t[P * D];
    if (s0 >= 0 && s0 <= SEQ - P) {
        const float4* p = reinterpret_cast<const float4*>(xbase + (size_t)s0 * D);
#pragma unroll
        for (int k = 0; k < P * D / 4; k++) reinterpret_cast<float4*>(t)[k] = p[k];
    } else {
#pragma unroll
        for (int i = 0; i < P; i++) {
            int sc = min(max(s0 + i, 0), SEQ - 1);
            const float2* p = reinterpret_cast<const float2*>(xbase + (size_t)sc * D);
            float2 a0 = p[0], a1 = p[1], a2 = p[2];
            t[i * D + 0] = a0.x; t[i * D + 1] = a0.y; t[i * D + 2] = a1.x;
            t[i * D + 3] = a1.y; t[i * D + 4] = a2.x; t[i * D + 5] = a2.y;
        }
    }

    // ---------------- weight staging (packed broadcast pairs) ----------------
    for (int i = tid; i < L * DFF * D; i += TPB) {
        int l = i / (DFF * D), f = (i / D) % DFF, d = i % D;
        float v = g_w1[i];
        sm.w1p[l][f][d] = pk(v, v);
    }
    for (int i = tid; i < L * DFF; i += TPB) {
        float v = g_b1[i];
        sm.w1p[i / DFF][i % DFF][6] = pk(v, v);
    }
    for (int i = tid; i < L * D * DFF; i += TPB) {
        int l = i / (D * DFF), d = (i / DFF) % D, f = i % DFF;
        float v = g_w2[i];
        sm.w2p[l][f][d] = pk(v, v);
    }
    for (int i = tid; i < 2 * L * D; i += TPB) {
        int la = i / D, d = i % D;
        sm.attp[la][0][d] = pk(g_qw[i], g_qw[i]);
        sm.attp[la][1][d] = pk(g_qb[i], g_qb[i]);
        sm.attp[la][2][d] = pk(g_kw[i], g_kw[i]);
        sm.attp[la][3][d] = pk(g_kb[i], g_kb[i]);
        sm.attp[la][4][d] = pk(g_vw[i], g_vw[i]);
        sm.attp[la][5][d] = pk(g_vb[i], g_vb[i]);
        sm.attp[la][6][d] = pk(g_mlw[i], g_mlw[i]);
        sm.attp[la][7][d] = pk(g_mlb[i], g_mlb[i]);
    }
    for (int i = tid; i < L * D; i += TPB) {
        int l = i / D, d = i % D;
        sm.ffnlnp[l][0][d] = pk(g_flw[i], g_flw[i]);
        sm.ffnlnp[l][1][d] = pk(g_flb[i], g_flb[i]);
        sm.b2p[l][d] = pk(g_b2[i], g_b2[i]);
    }
    if (tid < D) {
        sm.decp[0][tid] = pk(g_dec_w[tid], g_dec_w[tid]);
        sm.decp[1][tid] = pk(g_dec_b[tid], g_dec_b[tid]);
    }
    __syncthreads();   // the only block-wide sync

    // ---------------- packed state ----------------
    u64 x01[D], x23[D];
#pragma unroll
    for (int d = 0; d < D; d++) {
        x01[d] = pk(t[0 * D + d], t[1 * D + d]);
        x23[d] = pk(t[2 * D + d], t[3 * D + d]);
    }

    ln6p(x01, &sm.decp[0][0], &sm.decp[1][0]);
    ln6p(x23, &sm.decp[0][0], &sm.decp[1][0]);

    const bool edgeL = (s0 == 0);
    const bool edgeR = (s0 == SEQ - P);
    const u64 INV2  = pk(INV_S, INV_S);
    const u64 NINV2 = pk(-INV_S, -INV_S);

#pragma unroll 1
    for (int l = 0; l < L; l++) {
        // ---------------- two attention+LN stages (shfl exchange, in place) ----------------
#pragma unroll
        for (int a = 0; a < 2; a++) {
            const u64* ap = &sm.attp[l * 2 + a][0][0];
#pragma unroll
            for (int d = 0; d < D; d++) {
                float2 lo = up(x01[d]);           // lo.x = x0, lo.y = x1
                float2 hi = up(x23[d]);           // hi.x = x2, hi.y = x3
                float xm1 = __shfl_up_sync(FULL, hi.y, 1);
                float xp1 = __shfl_down_sync(FULL, lo.x, 1);
                if (edgeL) xm1 = lo.x;
                if (edgeR) xp1 = hi.y;
                u64 l01 = pk(xm1, lo.x);
                u64 m12 = pk(lo.y, hi.x);
                u64 r23 = pk(hi.y, xp1);
                u64 qw = ap[0 * 8 + d], qb = ap[1 * 8 + d];
                u64 kw = ap[2 * 8 + d], kb = ap[3 * 8 + d];
                u64 vw = ap[4 * 8 + d], vb = ap[5 * 8 + d];
                u64 q01 = f2fma(x01[d], qw, qb);
                u64 q23 = f2fma(x23[d], qw, qb);
                u64 k01 = f2fma(l01, kw, kb);
                u64 k23 = f2fma(m12, kw, kb);
                u64 v01 = f2fma(m12, vw, vb);
                u64 v23 = f2fma(r23, vw, vb);
                x01[d] = f2fma(f2mul(q01, q01), INV2, f2fma(f2mul(k01, v01), NINV2, x01[d]));
                x23[d] = f2fma(f2mul(q23, q23), INV2, f2fma(f2mul(k23, v23), NINV2, x23[d]));
            }
            ln6p(x01, ap + 6 * 8, ap + 7 * 8);
            ln6p(x23, ap + 6 * 8, ap + 7 * 8);
        }

        // ---------------- FFN (packed, weights pre-paired in shared) ----------------
        u64 y01[D], y23[D];
#pragma unroll
        for (int d = 0; d < D; d++) {
            u64 b2 = sm.b2p[l][d];
            y01[d] = f2add(x01[d], b2);
            y23[d] = f2add(x23[d], b2);
        }
        const u64* w1r = &sm.w1p[l][0][0];
        const u64* w2r = &sm.w2p[l][0][0];
#pragma unroll 8
        for (int f = 0; f < DFF; f++) {
            ulonglong2 wa = *reinterpret_cast<const ulonglong2*>(w1r + f * 8 + 0);
            ulonglong2 wb = *reinterpret_cast<const ulonglong2*>(w1r + f * 8 + 2);
            ulonglong2 wc = *reinterpret_cast<const ulonglong2*>(w1r + f * 8 + 4);
            u64 b1 = w1r[f * 8 + 6];
            u64 h01 = f2fma(x01[0], wa.x, b1);
            u64 h23 = f2fma(x23[0], wa.x, b1);
            h01 = f2fma(x01[1], wa.y, h01);  h23 = f2fma(x23[1], wa.y, h23);
            h01 = f2fma(x01[2], wb.x, h01);  h23 = f2fma(x23[2], wb.x, h23);
            h01 = f2fma(x01[3], wb.y, h01);  h23 = f2fma(x23[3], wb.y, h23);
            h01 = f2fma(x01[4], wc.x, h01);  h23 = f2fma(x23[4], wc.x, h23);
            h01 = f2fma(x01[5], wc.y, h01);  h23 = f2fma(x23[5], wc.y, h23);
            h01 = relu2(h01);
            h23 = relu2(h23);
            ulonglong2 va = *reinterpret_cast<const ulonglong2*>(w2r + f * 8 + 0);
            ulonglong2 vb = *reinterpret_cast<const ulonglong2*>(w2r + f * 8 + 2);
            ulonglong2 vc = *reinterpret_cast<const ulonglong2*>(w2r + f * 8 + 4);
            y01[0] = f2fma(h01, va.x, y01[0]);  y23[0] = f2fma(h23, va.x, y23[0]);
            y01[1] = f2fma(h01, va.y, y01[1]);  y23[1] = f2fma(h23, va.y, y23[1]);
            y01[2] = f2fma(h01, vb.x, y01[2]);  y23[2] = f2fma(h23, vb.x, y23[2]);
            y01[3] = f2fma(h01, vb.y, y01[3]);  y23[3] = f2fma(h23, vb.y, y23[3]);
            y01[4] = f2fma(h01, vc.x, y01[4]);  y23[4] = f2fma(h23, vc.x, y23[4]);
            y01[5] = f2fma(h01, vc.y, y01[5]);  y23[5] = f2fma(h23, vc.y, y23[5]);
        }
        ln6p(y01, &sm.ffnlnp[l][0][0], &sm.ffnlnp[l][1][0]);
        ln6p(y23, &sm.ffnlnp[l][0][0], &sm.ffnlnp[l][1][0]);
#pragma unroll
        for (int d = 0; d < D; d++) { x01[d] = y01[d]; x23[d] = y23[d]; }
    }

    // ---------------- write interior (lanes 2..29) ----------------
    if (lane >= 2 && lane < 30) {
#pragma unroll
        for (int d = 0; d < D; d++) {
            float2 a = up(x01[d]), b = up(x23[d]);
            t[0 * D + d] = a.x; t[1 * D + d] = a.y;
            t[2 * D + d] = b.x; t[3 * D + d] = b.y;
        }
        float4* o = reinterpret_cast<float4*>(g_out + ((size_t)row * SEQ + s0) * D);
#pragma unroll
        for (int k = 0; k < P * D / 4; k++) o[k] = reinterpret_cast<float4*>(t)[k];
    }
}

extern "C" void kernel_launch(void* const* d_in, const int* in_sizes, int n_in,
                              void* d_out, int out_size) {
    decoder_fused_kernel<<<NBLK, TPB>>>(
        (const float*)d_in[0],
        (const float*)d_in[2],  (const float*)d_in[3],
        (const float*)d_in[4],  (const float*)d_in[5],
        (const float*)d_in[6],  (const float*)d_in[7],
        (const float*)d_in[8],  (const float*)d_in[9],
        (const float*)d_in[12], (const float*)d_in[13],
        (const float*)d_in[14], (const float*)d_in[15],
        (const float*)d_in[16], (const float*)d_in[17],
        (const float*)d_in[18], (const float*)d_in[19],
        (float*)d_out);
}